// round 5
// baseline (speedup 1.0000x reference)
#include <cuda_runtime.h>

#define Hh 2048
#define Ww 2048
#define HW (Hh * Ww)
#define TX 32
#define TY 16
#define SX 34
#define SY 18
#define SN (SX * SY)

// Scratch: src = A*mass + |force| plane (static __device__ per allocation rules)
__device__ float g_src[HW];
// g_w[0..8] = k0+k1 combined 3x3, g_w[9..17] = 0.5*(k2+k3), g_w[18] = kc
__device__ float g_w[19];

// ---------------------------------------------------------------------------
// Prep: combine conv kernels, compute kc = 1/sum(|kernel|)
// ---------------------------------------------------------------------------
__global__ void prep_kernel(const float* __restrict__ k) {
    if (threadIdx.x == 0 && blockIdx.x == 0) {
        float s = 0.0f;
        for (int j = 0; j < 36; ++j) s += fabsf(k[j]);
        g_w[18] = 1.0f / s;
        for (int j = 0; j < 9; ++j) {
            g_w[j]     = k[j] + k[9 + j];
            g_w[9 + j] = 0.5f * (k[18 + j] + k[27 + j]);
        }
    }
}

// ---------------------------------------------------------------------------
// Pass 1: src = A*mass + sqrt(fx^2 + fy^2), vectorized
// ---------------------------------------------------------------------------
__global__ __launch_bounds__(256) void src_kernel(const float4* __restrict__ mass,
                                                  const float4* __restrict__ A,
                                                  const float4* __restrict__ force) {
    int i = blockIdx.x * blockDim.x + threadIdx.x;
    float4 m = mass[i];
    float4 a = A[i];
    float4 fx = force[i];
    float4 fy = force[HW / 4 + i];
    float4 r;
    r.x = a.x * m.x + sqrtf(fx.x * fx.x + fy.x * fy.x);
    r.y = a.y * m.y + sqrtf(fx.y * fx.y + fy.y * fy.y);
    r.z = a.z * m.z + sqrtf(fx.z * fx.z + fy.z * fy.z);
    r.w = a.w * m.w + sqrtf(fx.w * fx.w + fy.w * fy.w);
    reinterpret_cast<float4*>(g_src)[i] = r;
}

// ---------------------------------------------------------------------------
// Pass 2 (fused): conv -> force update -> momentum/velocity -> softmax props
// staged in smem with 1-halo -> 3x3 gather -> new_mass / new_momentum.
// Tile: 32x16 output, staged region 34x18.
// ---------------------------------------------------------------------------
__global__ __launch_bounds__(256) void main_kernel(const float* __restrict__ mass,
                                                   const float* __restrict__ mom,
                                                   const float* __restrict__ force,
                                                   float* __restrict__ out) {
    __shared__ float sp[9][SN];   // propagation weights
    __shared__ float smm[SN];     // mass
    __shared__ float smx[SN];     // updated momentum x
    __shared__ float smy[SN];     // updated momentum y

    float w0[9], w1[9];
#pragma unroll
    for (int j = 0; j < 9; ++j) { w0[j] = g_w[j]; w1[j] = g_w[9 + j]; }
    const float kc  = g_w[18];
    const float SQ2 = 0.70710678118654752f;

    const int tx0 = blockIdx.x * TX;
    const int ty0 = blockIdx.y * TY;
    const int tid = threadIdx.x;

    // ---- Stage: compute per-pixel state for the (TX+2)x(TY+2) halo region ----
    for (int s = tid; s < SN; s += 256) {
        int sy = s / SX;
        int sx = s - sy * SX;
        int gx = tx0 + sx - 1;
        if (gx < 0) gx += Ww; else if (gx >= Ww) gx -= Ww;
        int gy = ty0 + sy - 1;
        if (gy < 0) gy += Hh; else if (gy >= Hh) gy -= Hh;

        int xm = (gx == 0)      ? Ww - 1 : gx - 1;
        int xp = (gx == Ww - 1) ? 0      : gx + 1;
        int ym = (gy == 0)      ? Hh - 1 : gy - 1;
        int yp = (gy == Hh - 1) ? 0      : gy + 1;

        const float* rm = g_src + (size_t)ym * Ww;
        const float* rc = g_src + (size_t)gy * Ww;
        const float* rp = g_src + (size_t)yp * Ww;

        float s00 = rm[xm], s01 = rm[gx], s02 = rm[xp];
        float s10 = rc[xm], s11 = rc[gx], s12 = rc[xp];
        float s20 = rp[xm], s21 = rp[gx], s22 = rp[xp];

        float nf0 = s00 * w0[0] + s01 * w0[1] + s02 * w0[2]
                  + s10 * w0[3] + s11 * w0[4] + s12 * w0[5]
                  + s20 * w0[6] + s21 * w0[7] + s22 * w0[8];
        float nf1 = s00 * w1[0] + s01 * w1[1] + s02 * w1[2]
                  + s10 * w1[3] + s11 * w1[4] + s12 * w1[5]
                  + s20 * w1[6] + s21 * w1[7] + s22 * w1[8];

        int g = gy * Ww + gx;
        float fx = force[g];
        float fy = force[HW + g];
        float fnx = fx + (nf0 - fx) * kc;
        float fny = fy + (nf1 - fy) * kc;

        float ms = mass[g];
        bool alive = !(ms < 1e-8f);
        float mnx = alive ? (mom[g] + fnx)      : 0.0f;
        float mny = alive ? (mom[HW + g] + fny) : 0.0f;
        float vx  = alive ? (mnx / ms) : 0.0f;
        float vy  = alive ? (mny / ms) : 0.0f;

        // logits = 0.1 * (DIR . v); set is { l0, l1, l2, l3, 0, -l3, -l2, -l1, -l0 }
        float sv = SQ2 * vx, sw = SQ2 * vy;
        float l0 = (sv + sw) * 0.1f;   // dir ( SQ2,  SQ2)
        float l1 = vy * 0.1f;          // dir (   0,    1)
        float l2 = (sw - sv) * 0.1f;   // dir (-SQ2,  SQ2)
        float l3 = vx * 0.1f;          // dir (   1,    0)

        float mx = fmaxf(fmaxf(fabsf(l0), fabsf(l1)), fmaxf(fabsf(l2), fabsf(l3)));
        float e0 = __expf(l0 - mx);
        float e1 = __expf(l1 - mx);
        float e2 = __expf(l2 - mx);
        float e3 = __expf(l3 - mx);
        float e4 = __expf(-mx);
        float e5 = __expf(-l3 - mx);
        float e6 = __expf(-l2 - mx);
        float e7 = __expf(-l1 - mx);
        float e8 = __expf(-l0 - mx);
        float sum = ((e0 + e1) + (e2 + e3)) + ((e4 + e5) + (e6 + e7)) + e8;
        float inv = 1.0f / sum;

        sp[0][s] = e0 * inv;
        sp[1][s] = e1 * inv;
        sp[2][s] = e2 * inv;
        sp[3][s] = e3 * inv;
        sp[4][s] = e4 * inv;
        sp[5][s] = e5 * inv;
        sp[6][s] = e6 * inv;
        sp[7][s] = e7 * inv;
        sp[8][s] = e8 * inv;
        smm[s] = ms;
        smx[s] = mnx;
        smy[s] = mny;

        // force output (center pixels only; each pixel owned by exactly one tile)
        if (sx >= 1 && sx <= TX && sy >= 1 && sy <= TY) {
            out[3 * HW + g] = fnx;
            out[4 * HW + g] = fny;
        }
    }
    __syncthreads();

    // ---- Gather: new_mass / new_momentum via 3x3 MOVES (circular shifts) ----
    const int ltx = tid & 31;
    const int lty = tid >> 5;
#pragma unroll
    for (int oy = lty; oy < TY; oy += 8) {
        int base = (oy + 1) * SX + (ltx + 1);
        float nm = 0.0f, nx = 0.0f, ny = 0.0f;
#pragma unroll
        for (int i = 0; i < 9; ++i) {
            // MOVES[i] hot at (r,c): offset (dy,dx) = (r-1, c-1) = (1 - i/3 ... )
            const int dy = 1 - i / 3;
            const int dx = 1 - i % 3;
            int idx = base + dy * SX + dx;
            float p = sp[i][idx];
            nm = fmaf(smm[idx], p, nm);
            nx = fmaf(smx[idx], p, nx);
            ny = fmaf(smy[idx], p, ny);
        }
        int g = (ty0 + oy) * Ww + (tx0 + ltx);
        out[g]          = nm;   // normalization factor == 1 to ~1e-6 (see theory)
        out[HW + g]     = nx;
        out[2 * HW + g] = ny;
    }
}

// ---------------------------------------------------------------------------
extern "C" void kernel_launch(void* const* d_in, const int* in_sizes, int n_in,
                              void* d_out, int out_size) {
    const float* mass = (const float*)d_in[0];   // (1,1,H,W)
    const float* mom  = (const float*)d_in[1];   // (2,1,H,W)
    const float* forc = (const float*)d_in[2];   // (2,1,H,W)
    const float* A    = (const float*)d_in[3];   // (1,1,H,W)
    const float* kern = (const float*)d_in[4];   // (4,1,3,3)
    float* out = (float*)d_out;                  // [new_mass | new_momentum(2) | force(2)]

    prep_kernel<<<1, 32>>>(kern);
    src_kernel<<<HW / 4 / 256, 256>>>((const float4*)mass, (const float4*)A,
                                      (const float4*)forc);
    dim3 grid(Ww / TX, Hh / TY);
    main_kernel<<<grid, 256>>>(mass, mom, forc, out);
}

// round 6
// speedup vs baseline: 1.2087x; 1.2087x over previous
#include <cuda_runtime.h>

#define Hh 2048
#define Ww 2048
#define HW (Hh * Ww)
#define TX 32
#define TY 16
#define P1X 34
#define P1Y 18
#define P1N (P1X * P1Y)   // 612 : region needing softmax/props (1-halo)
#define P2X 36
#define P2Y 20
#define P2N (P2X * P2Y)   // 720 : region needing src (2-halo)

// ---------------------------------------------------------------------------
// Fully fused step:
//   phase A: stage src = A*mass + |force| (+ mass, fx, fy) for 36x20 region
//   phase B: conv(src) -> force update -> momentum/velocity -> softmax props
//   phase C: 3x3 one-hot-shift gather -> new_mass / new_momentum
// Global renormalization skipped: softmax rows sum to 1 and MOVES are pure
// circular shifts, so sum(new_mass) == sum(mass) to ~1e-7.
// ---------------------------------------------------------------------------
__global__ __launch_bounds__(256) void step_kernel(
    const float* __restrict__ mass, const float* __restrict__ mom,
    const float* __restrict__ force, const float* __restrict__ A,
    const float* __restrict__ kern, float* __restrict__ out)
{
    __shared__ float s_src[P2N];
    __shared__ float s_m[P2N];
    __shared__ float s_fx[P2N];
    __shared__ float s_fy[P2N];
    __shared__ float sp[9][P1N];   // propagation weights
    __shared__ float smx[P1N];     // updated momentum x
    __shared__ float smy[P1N];     // updated momentum y
    __shared__ float s_w[19];      // w0[9], w1[9], kc

    const int tid = threadIdx.x;
    const int tx0 = blockIdx.x * TX;
    const int ty0 = blockIdx.y * TY;

    // combined conv weights (k0+k1, 0.5*(k2+k3)) + kc, computed per block
    if (tid == 0) {
        float ssum = 0.0f;
        #pragma unroll
        for (int j = 0; j < 36; ++j) ssum += fabsf(kern[j]);
        s_w[18] = 1.0f / ssum;
        #pragma unroll
        for (int j = 0; j < 9; ++j) {
            s_w[j]     = kern[j] + kern[9 + j];
            s_w[9 + j] = 0.5f * (kern[18 + j] + kern[27 + j]);
        }
    }

    // ---- Phase A: stage pointwise inputs for the 2-halo region (36x20) ----
    for (int s = tid; s < P2N; s += 256) {
        int sy = s / P2X, sx = s - sy * P2X;
        int gx = tx0 + sx - 2; if (gx < 0) gx += Ww; else if (gx >= Ww) gx -= Ww;
        int gy = ty0 + sy - 2; if (gy < 0) gy += Hh; else if (gy >= Hh) gy -= Hh;
        int g = gy * Ww + gx;
        float m  = mass[g];
        float a  = A[g];
        float fx = force[g];
        float fy = force[HW + g];
        s_m[s]  = m;
        s_fx[s] = fx;
        s_fy[s] = fy;
        s_src[s] = fmaf(a, m, sqrtf(fmaf(fx, fx, fy * fy)));
    }
    __syncthreads();

    float w0[9], w1[9];
    #pragma unroll
    for (int j = 0; j < 9; ++j) { w0[j] = s_w[j]; w1[j] = s_w[9 + j]; }
    const float kc   = s_w[18];
    const float SQ2T = 0.70710678118654752f * 0.1f;

    // ---- Phase B: per-pixel physics for the 1-halo region (34x18) ----
    for (int s = tid; s < P1N; s += 256) {
        int sy = s / P1X, sx = s - sy * P1X;
        int p2 = (sy + 1) * P2X + sx + 1;

        float nf0 = 0.0f, nf1 = 0.0f;
        #pragma unroll
        for (int r = 0; r < 3; ++r)
            #pragma unroll
            for (int c = 0; c < 3; ++c) {
                float v = s_src[p2 + (r - 1) * P2X + (c - 1)];
                nf0 = fmaf(v, w0[r * 3 + c], nf0);
                nf1 = fmaf(v, w1[r * 3 + c], nf1);
            }

        float fx = s_fx[p2], fy = s_fy[p2];
        float fnx = fx + (nf0 - fx) * kc;
        float fny = fy + (nf1 - fy) * kc;
        float ms = s_m[p2];

        int gx = tx0 + sx - 1; if (gx < 0) gx += Ww; else if (gx >= Ww) gx -= Ww;
        int gy = ty0 + sy - 1; if (gy < 0) gy += Hh; else if (gy >= Hh) gy -= Hh;
        int g = gy * Ww + gx;

        bool alive = !(ms < 1e-8f);
        float mnx = alive ? (mom[g] + fnx)      : 0.0f;
        float mny = alive ? (mom[HW + g] + fny) : 0.0f;
        float vx  = alive ? (mnx / ms) : 0.0f;
        float vy  = alive ? (mny / ms) : 0.0f;

        // logits: { l0, l1, l2, l3, 0, -l3, -l2, -l1, -l0 } with temp folded in
        float sv = SQ2T * vx, sw = SQ2T * vy;
        float l0 = sv + sw;
        float l1 = 0.1f * vy;
        float l2 = sw - sv;
        float l3 = 0.1f * vx;

        float mx = fmaxf(fmaxf(fabsf(l0), fabsf(l1)), fmaxf(fabsf(l2), fabsf(l3)));
        float e0 = __expf(l0 - mx);
        float e1 = __expf(l1 - mx);
        float e2 = __expf(l2 - mx);
        float e3 = __expf(l3 - mx);
        float e4 = __expf(-mx);
        float e5 = __expf(-l3 - mx);
        float e6 = __expf(-l2 - mx);
        float e7 = __expf(-l1 - mx);
        float e8 = __expf(-l0 - mx);
        float inv = 1.0f / (((e0 + e1) + (e2 + e3)) + ((e4 + e5) + (e6 + e7)) + e8);

        sp[0][s] = e0 * inv;  sp[1][s] = e1 * inv;  sp[2][s] = e2 * inv;
        sp[3][s] = e3 * inv;  sp[4][s] = e4 * inv;  sp[5][s] = e5 * inv;
        sp[6][s] = e6 * inv;  sp[7][s] = e7 * inv;  sp[8][s] = e8 * inv;
        smx[s] = mnx;
        smy[s] = mny;

        // force output — center pixels only (owned by exactly one tile)
        if (sx >= 1 && sx <= TX && sy >= 1 && sy <= TY) {
            out[3 * HW + g] = fnx;
            out[4 * HW + g] = fny;
        }
    }
    __syncthreads();

    // ---- Phase C: 3x3 circular-shift gather (MOVES conv) ----
    const int ltx = tid & 31;
    const int lty = tid >> 5;
    #pragma unroll
    for (int oy = lty; oy < TY; oy += 8) {
        int base1 = (oy + 1) * P1X + ltx + 1;   // P1 index of output pixel
        int base2 = (oy + 2) * P2X + ltx + 2;   // P2 index of output pixel
        float nm = 0.0f, nx = 0.0f, ny = 0.0f;
        #pragma unroll
        for (int i = 0; i < 9; ++i) {
            const int dy = 1 - i / 3;
            const int dx = 1 - i % 3;
            int i1 = base1 + dy * P1X + dx;
            int i2 = base2 + dy * P2X + dx;
            float p = sp[i][i1];
            nm = fmaf(s_m[i2], p, nm);
            nx = fmaf(smx[i1], p, nx);
            ny = fmaf(smy[i1], p, ny);
        }
        int g = (ty0 + oy) * Ww + tx0 + ltx;
        out[g]          = nm;
        out[HW + g]     = nx;
        out[2 * HW + g] = ny;
    }
}

// ---------------------------------------------------------------------------
extern "C" void kernel_launch(void* const* d_in, const int* in_sizes, int n_in,
                              void* d_out, int out_size) {
    const float* mass = (const float*)d_in[0];   // (1,1,H,W)
    const float* mom  = (const float*)d_in[1];   // (2,1,H,W)
    const float* forc = (const float*)d_in[2];   // (2,1,H,W)
    const float* A    = (const float*)d_in[3];   // (1,1,H,W)
    const float* kern = (const float*)d_in[4];   // (4,1,3,3)
    float* out = (float*)d_out;                  // [new_mass | new_mom(2) | force(2)]

    dim3 grid(Ww / TX, Hh / TY);
    step_kernel<<<grid, 256>>>(mass, mom, forc, A, kern, out);
}

// round 7
// speedup vs baseline: 1.2417x; 1.0273x over previous
#include <cuda_runtime.h>

#define Hh 2048
#define Ww 2048
#define HW (Hh * Ww)
#define TX 32
#define TY 16
#define GBX (Ww / TX)      // 64
#define GBY (Hh / TY)      // 128
#define P1X 34
#define P1Y 18
#define P1N (P1X * P1Y)    // 612 : 1-halo region (props / state)
#define SRCX 40            // padded, 16B-aligned staging for src (2-halo + vec align)
#define SRCY 20

// ---------------------------------------------------------------------------
// Fully fused step (see round-4/5 derivation):
//  - global renormalization skipped (softmax rows sum to 1, MOVES are pure
//    circular shifts => sum(new_mass)==sum(mass) to ~1e-7)
//  - 4 conv kernels combined to 2 (k0+k1, 0.5*(k2+k3))
// ---------------------------------------------------------------------------
__global__ void __launch_bounds__(256, 5) step_kernel(
    const float* __restrict__ mass, const float* __restrict__ mom,
    const float* __restrict__ force, const float* __restrict__ A,
    const float* __restrict__ kern, float* __restrict__ out)
{
    __shared__ float s_src[SRCY * SRCX];
    __shared__ float sp[9][P1N];   // propagation weights
    __shared__ float s_m[P1N];     // mass (P1 indexing)
    __shared__ float smx[P1N];     // updated momentum x
    __shared__ float smy[P1N];     // updated momentum y
    __shared__ float s_w[19];      // w0[9], w1[9], kc

    const int tid = threadIdx.x;
    const int bx = blockIdx.x, by = blockIdx.y;
    const int tx0 = bx * TX;
    const int ty0 = by * TY;
    const bool interior = (bx >= 1) & (bx <= GBX - 2) & (by >= 1) & (by <= GBY - 2);

    if (tid == 0) {
        float ssum = 0.0f;
        #pragma unroll
        for (int j = 0; j < 36; ++j) ssum += fabsf(kern[j]);
        s_w[18] = 1.0f / ssum;
        #pragma unroll
        for (int j = 0; j < 9; ++j) {
            s_w[j]     = kern[j] + kern[9 + j];
            s_w[9 + j] = 0.5f * (kern[18 + j] + kern[27 + j]);
        }
    }

    // ---- Phase A: stage src = A*mass + |force| over 40x20 (2-halo, padded) ----
    if (interior) {
        const float4* m4 = (const float4*)mass;
        const float4* a4 = (const float4*)A;
        const float4* f4 = (const float4*)force;
        const int c0 = (tx0 - 4) >> 2;           // first float4 column
        #pragma unroll
        for (int i = tid; i < SRCY * SRCX / 4; i += 256) {   // 200 float4
            int r = i / (SRCX / 4), c = i - r * (SRCX / 4);
            int g4 = (ty0 - 2 + r) * (Ww / 4) + c0 + c;
            float4 m = m4[g4], a = a4[g4];
            float4 fx = f4[g4], fy = f4[HW / 4 + g4];
            float4 s;
            s.x = fmaf(a.x, m.x, sqrtf(fmaf(fx.x, fx.x, fy.x * fy.x)));
            s.y = fmaf(a.y, m.y, sqrtf(fmaf(fx.y, fx.y, fy.y * fy.y)));
            s.z = fmaf(a.z, m.z, sqrtf(fmaf(fx.z, fx.z, fy.z * fy.z)));
            s.w = fmaf(a.w, m.w, sqrtf(fmaf(fx.w, fx.w, fy.w * fy.w)));
            ((float4*)s_src)[i] = s;
        }
    } else {
        for (int i = tid; i < SRCY * SRCX; i += 256) {
            int r = i / SRCX, c = i - r * SRCX;
            int gx = tx0 - 4 + c; if (gx < 0) gx += Ww; else if (gx >= Ww) gx -= Ww;
            int gy = ty0 - 2 + r; if (gy < 0) gy += Hh; else if (gy >= Hh) gy -= Hh;
            int g = gy * Ww + gx;
            float m = mass[g], a = A[g];
            float fx = force[g], fy = force[HW + g];
            s_src[i] = fmaf(a, m, sqrtf(fmaf(fx, fx, fy * fy)));
        }
    }
    __syncthreads();

    float w0[9], w1[9];
    #pragma unroll
    for (int j = 0; j < 9; ++j) { w0[j] = s_w[j]; w1[j] = s_w[9 + j]; }
    const float kc   = s_w[18];
    const float SQ2T = 0.70710678118654752f * 0.1f;

    // ---- Phase B: physics + softmax for the 1-halo region (34x18) ----
    for (int s = tid; s < P1N; s += 256) {
        int sy = s / P1X, sx = s - sy * P1X;
        int p2 = (sy + 1) * SRCX + sx + 3;   // src index of this pixel

        float nf0 = 0.0f, nf1 = 0.0f;
        #pragma unroll
        for (int r = 0; r < 3; ++r)
            #pragma unroll
            for (int c = 0; c < 3; ++c) {
                float v = s_src[p2 + (r - 1) * SRCX + (c - 1)];
                nf0 = fmaf(v, w0[r * 3 + c], nf0);
                nf1 = fmaf(v, w1[r * 3 + c], nf1);
            }

        int g;
        if (interior) {
            g = (ty0 + sy - 1) * Ww + tx0 + sx - 1;
        } else {
            int gx = tx0 + sx - 1; if (gx < 0) gx += Ww; else if (gx >= Ww) gx -= Ww;
            int gy = ty0 + sy - 1; if (gy < 0) gy += Hh; else if (gy >= Hh) gy -= Hh;
            g = gy * Ww + gx;
        }

        float fx = force[g], fy = force[HW + g];
        float fnx = fx + (nf0 - fx) * kc;
        float fny = fy + (nf1 - fy) * kc;
        float ms = mass[g];

        bool alive = !(ms < 1e-8f);
        float mnx = alive ? (mom[g] + fnx)      : 0.0f;
        float mny = alive ? (mom[HW + g] + fny) : 0.0f;
        float inv_ms = 1.0f / ms;
        float vx = alive ? (mnx * inv_ms) : 0.0f;
        float vy = alive ? (mny * inv_ms) : 0.0f;

        // logits: { l0, l1, l2, l3, 0, -l3, -l2, -l1, -l0 } (temp folded in)
        float sv = SQ2T * vx, sw = SQ2T * vy;
        float l0 = sv + sw;
        float l1 = 0.1f * vy;
        float l2 = sw - sv;
        float l3 = 0.1f * vx;

        float mx = fmaxf(fmaxf(fabsf(l0), fabsf(l1)), fmaxf(fabsf(l2), fabsf(l3)));
        float e0 = __expf(l0 - mx);
        float e1 = __expf(l1 - mx);
        float e2 = __expf(l2 - mx);
        float e3 = __expf(l3 - mx);
        float e4 = __expf(-mx);
        float e5 = __expf(-l3 - mx);
        float e6 = __expf(-l2 - mx);
        float e7 = __expf(-l1 - mx);
        float e8 = __expf(-l0 - mx);
        float inv = 1.0f / (((e0 + e1) + (e2 + e3)) + ((e4 + e5) + (e6 + e7)) + e8);

        sp[0][s] = e0 * inv;  sp[1][s] = e1 * inv;  sp[2][s] = e2 * inv;
        sp[3][s] = e3 * inv;  sp[4][s] = e4 * inv;  sp[5][s] = e5 * inv;
        sp[6][s] = e6 * inv;  sp[7][s] = e7 * inv;  sp[8][s] = e8 * inv;
        s_m[s] = ms;
        smx[s] = mnx;
        smy[s] = mny;

        if (sx >= 1 && sx <= TX && sy >= 1 && sy <= TY) {
            out[3 * HW + g] = fnx;
            out[4 * HW + g] = fny;
        }
    }
    __syncthreads();

    // ---- Phase C: 3x3 gather, 2-row strip per thread with m/mom row caching ----
    // term(pixel oy, dy, dx) uses plane i=(1-dy)*3+(1-dx) and value at
    // P1 position (oy+1+dy, ox+1+dx). Staged row r = P1 row oyA + r.
    {
        const int ltx = tid & 31;
        const int lty = tid >> 5;
        const int oyA = lty * 2;          // thread handles output rows oyA, oyA+1
        float amA = 0.f, axA = 0.f, ayA = 0.f;
        float amB = 0.f, axB = 0.f, ayB = 0.f;

        #pragma unroll
        for (int r = 0; r < 4; ++r) {
            int rb = (oyA + r) * P1X + ltx;   // P1 col ltx == output col ltx-1+... (dx=-1 slot)
            float qm0 = s_m[rb], qm1 = s_m[rb + 1], qm2 = s_m[rb + 2];
            float qx0 = smx[rb], qx1 = smx[rb + 1], qx2 = smx[rb + 2];
            float qy0 = smy[rb], qy1 = smy[rb + 1], qy2 = smy[rb + 2];

            if (r <= 2) {   // contributes to pixel A with dy = r-1, plane base (2-r)*3
                float p;
                p = sp[(2 - r) * 3 + 0][rb + 2];   // dx=+1
                amA = fmaf(qm2, p, amA); axA = fmaf(qx2, p, axA); ayA = fmaf(qy2, p, ayA);
                p = sp[(2 - r) * 3 + 1][rb + 1];   // dx=0
                amA = fmaf(qm1, p, amA); axA = fmaf(qx1, p, axA); ayA = fmaf(qy1, p, ayA);
                p = sp[(2 - r) * 3 + 2][rb];       // dx=-1
                amA = fmaf(qm0, p, amA); axA = fmaf(qx0, p, axA); ayA = fmaf(qy0, p, ayA);
            }
            if (r >= 1) {   // contributes to pixel B with dy = r-2, plane base (3-r)*3
                float p;
                p = sp[(3 - r) * 3 + 0][rb + 2];
                amB = fmaf(qm2, p, amB); axB = fmaf(qx2, p, axB); ayB = fmaf(qy2, p, ayB);
                p = sp[(3 - r) * 3 + 1][rb + 1];
                amB = fmaf(qm1, p, amB); axB = fmaf(qx1, p, axB); ayB = fmaf(qy1, p, ayB);
                p = sp[(3 - r) * 3 + 2][rb];
                amB = fmaf(qm0, p, amB); axB = fmaf(qx0, p, axB); ayB = fmaf(qy0, p, ayB);
            }
        }

        int gA = (ty0 + oyA) * Ww + tx0 + ltx;
        out[gA]               = amA;
        out[HW + gA]          = axA;
        out[2 * HW + gA]      = ayA;
        out[gA + Ww]          = amB;
        out[HW + gA + Ww]     = axB;
        out[2 * HW + gA + Ww] = ayB;
    }
}

// ---------------------------------------------------------------------------
extern "C" void kernel_launch(void* const* d_in, const int* in_sizes, int n_in,
                              void* d_out, int out_size) {
    const float* mass = (const float*)d_in[0];   // (1,1,H,W)
    const float* mom  = (const float*)d_in[1];   // (2,1,H,W)
    const float* forc = (const float*)d_in[2];   // (2,1,H,W)
    const float* A    = (const float*)d_in[3];   // (1,1,H,W)
    const float* kern = (const float*)d_in[4];   // (4,1,3,3)
    float* out = (float*)d_out;                  // [new_mass | new_mom(2) | force(2)]

    dim3 grid(GBX, GBY);
    step_kernel<<<grid, 256>>>(mass, mom, forc, A, kern, out);
}